// round 9
// baseline (speedup 1.0000x reference)
#include <cuda_runtime.h>
#include <mma.h>
#include <math.h>

using namespace nvcuda;

#define NNODES 50000
#define NEDGES 800000
#define MAXF   256
#define EPS    1e-5f

// ---------------- device scratch (no allocations allowed) ----------------
__device__ float g_bufA[(size_t)NNODES * MAXF];
__device__ float g_bufB[(size_t)NNODES * MAXF];
__device__ float g_dinv[NNODES];
__device__ int   g_deg[NNODES];
__device__ int   g_rowptr[NNODES + 1];
__device__ int   g_cursor[NNODES];
__device__ int2  g_csr[NEDGES];          // {src, coef-as-int-bits}
__device__ int   g_incl[NNODES];
__device__ int   g_bsums[64];

// ---------------- degree / dinv ----------------
__global__ void zero_deg_kernel(int* deg, int n) {
    int i = blockIdx.x * blockDim.x + threadIdx.x;
    if (i < n) deg[i] = 0;
}

__global__ void count_deg_kernel(const int* __restrict__ dst, int* deg, int E) {
    int i = blockIdx.x * blockDim.x + threadIdx.x;
    if (i < E) atomicAdd(&deg[dst[i]], 1);
}

__global__ void dinv_kernel(const int* __restrict__ deg, float* dinv, int n) {
    int i = blockIdx.x * blockDim.x + threadIdx.x;
    if (i < n) dinv[i] = rsqrtf((float)deg[i] + 1.0f);
}

// ---------------- multi-block scan (3 stages) ----------------
__global__ void scan_partial_kernel(const int* __restrict__ deg, int* incl, int* bsums, int n)
{
    __shared__ int warpsums[32];
    int i = blockIdx.x * 1024 + threadIdx.x;
    int lane = threadIdx.x & 31;
    int wid = threadIdx.x >> 5;
    int v = (i < n) ? deg[i] : 0;
    int x = v;
    #pragma unroll
    for (int o = 1; o < 32; o <<= 1) {
        int t = __shfl_up_sync(0xFFFFFFFFu, x, o);
        if (lane >= o) x += t;
    }
    if (lane == 31) warpsums[wid] = x;
    __syncthreads();
    if (wid == 0) {
        int s = warpsums[lane];
        #pragma unroll
        for (int o = 1; o < 32; o <<= 1) {
            int t = __shfl_up_sync(0xFFFFFFFFu, s, o);
            if (lane >= o) s += t;
        }
        warpsums[lane] = s;
    }
    __syncthreads();
    int inclv = x + (wid > 0 ? warpsums[wid - 1] : 0);
    if (i < n) incl[i] = inclv;
    if (threadIdx.x == 1023) bsums[blockIdx.x] = inclv;
}

__global__ void scan_bsums_kernel(int* bsums, int nb)
{
    if (threadIdx.x == 0) {
        int run = 0;
        for (int b = 0; b < nb; b++) {
            int t = bsums[b];
            bsums[b] = run;
            run += t;
        }
    }
}

__global__ void scan_finalize_kernel(const int* __restrict__ deg, const int* __restrict__ incl,
                                     const int* __restrict__ bsums,
                                     int* rowptr, int* cursor, int n)
{
    int i = blockIdx.x * blockDim.x + threadIdx.x;
    if (i >= n) return;
    int val = bsums[i >> 10] + incl[i];
    rowptr[i + 1] = val;
    cursor[i] = val - deg[i];
    if (i == 0) rowptr[0] = 0;
}

// ---------------- CSR fill (packed int2) ----------------
__global__ void fill_csr_kernel(const int* __restrict__ src, const int* __restrict__ dst,
                                const float* __restrict__ dinv, int* cursor,
                                int2* csr, int E)
{
    int e = blockIdx.x * blockDim.x + threadIdx.x;
    if (e >= E) return;
    int s = src[e];
    int d = dst[e];
    int p = atomicAdd(&cursor[d], 1);
    csr[p] = make_int2(s, __float_as_int(dinv[s] * dinv[d]));
}

// ---------------- TF32 wmma GEMM: C[M,Nc] = A[M,K] @ W[K,Nc] (+bias) ----------------
#define LDT 132

__global__ __launch_bounds__(256)
void gemm_tf32_kernel(const float* __restrict__ A, const float* __restrict__ W,
                      const float* __restrict__ bias, float* __restrict__ C,
                      int M, int K, int Nc, int addBias)
{
    __shared__ __align__(16) float As[16][LDT];
    __shared__ __align__(16) float Ws[16][LDT];
    __shared__ __align__(16) float scr[8][16 * 20];

    const int tid = threadIdx.x;
    const int wid = tid >> 5;
    const int lane = tid & 31;
    const int wr = wid >> 1;
    const int wc = wid & 1;
    const int rowBase = blockIdx.y * 128;
    const int colBase = blockIdx.x * 128;

    wmma::fragment<wmma::accumulator, 16, 16, 8, float> acc[2][4];
    #pragma unroll
    for (int i = 0; i < 2; i++)
        #pragma unroll
        for (int j = 0; j < 4; j++) wmma::fill_fragment(acc[i][j], 0.0f);

    for (int k0 = 0; k0 < K; k0 += 16) {
        #pragma unroll
        for (int t = 0; t < 2; t++) {
            int lin = t * 256 + tid;
            int r = lin >> 2;
            int c4 = lin & 3;
            float4 v = make_float4(0.f, 0.f, 0.f, 0.f);
            int gr = rowBase + r;
            if (gr < M)
                v = *(const float4*)(A + (size_t)gr * K + k0 + 4 * c4);
            As[4 * c4 + 0][r] = wmma::__float_to_tf32(v.x);
            As[4 * c4 + 1][r] = wmma::__float_to_tf32(v.y);
            As[4 * c4 + 2][r] = wmma::__float_to_tf32(v.z);
            As[4 * c4 + 3][r] = wmma::__float_to_tf32(v.w);
        }
        #pragma unroll
        for (int t = 0; t < 2; t++) {
            int lin = t * 256 + tid;
            int r = lin >> 5;
            int c4 = lin & 31;
            float4 v = make_float4(0.f, 0.f, 0.f, 0.f);
            int gc = colBase + 4 * c4;
            if (gc + 3 < Nc)
                v = *(const float4*)(W + (size_t)(k0 + r) * Nc + gc);
            v.x = wmma::__float_to_tf32(v.x);
            v.y = wmma::__float_to_tf32(v.y);
            v.z = wmma::__float_to_tf32(v.z);
            v.w = wmma::__float_to_tf32(v.w);
            *(float4*)&Ws[r][4 * c4] = v;
        }
        __syncthreads();

        #pragma unroll
        for (int ks = 0; ks < 16; ks += 8) {
            wmma::fragment<wmma::matrix_a, 16, 16, 8, wmma::precision::tf32, wmma::col_major> af[2];
            wmma::fragment<wmma::matrix_b, 16, 16, 8, wmma::precision::tf32, wmma::row_major> bf[4];
            #pragma unroll
            for (int i = 0; i < 2; i++)
                wmma::load_matrix_sync(af[i], &As[ks][wr * 32 + i * 16], LDT);
            #pragma unroll
            for (int j = 0; j < 4; j++)
                wmma::load_matrix_sync(bf[j], &Ws[ks][wc * 64 + j * 16], LDT);
            #pragma unroll
            for (int i = 0; i < 2; i++)
                #pragma unroll
                for (int j = 0; j < 4; j++)
                    wmma::mma_sync(acc[i][j], af[i], bf[j], acc[i][j]);
        }
        __syncthreads();
    }

    if (addBias) {
        for (int idx = tid; idx < 8 * LDT; idx += 256) {
            int k = idx / LDT;
            int m = idx % LDT;
            As[k][m] = (k == 0 && m < 128) ? 1.0f : 0.0f;
            float bv = 0.0f;
            if (k == 0 && m < 128 && colBase + m < Nc) bv = bias[colBase + m];
            Ws[k][m] = wmma::__float_to_tf32(bv);
        }
        __syncthreads();
        wmma::fragment<wmma::matrix_a, 16, 16, 8, wmma::precision::tf32, wmma::col_major> af;
        wmma::fragment<wmma::matrix_b, 16, 16, 8, wmma::precision::tf32, wmma::row_major> bf[4];
        #pragma unroll
        for (int j = 0; j < 4; j++)
            wmma::load_matrix_sync(bf[j], &Ws[0][wc * 64 + j * 16], LDT);
        #pragma unroll
        for (int i = 0; i < 2; i++) {
            wmma::load_matrix_sync(af, &As[0][wr * 32 + i * 16], LDT);
            #pragma unroll
            for (int j = 0; j < 4; j++)
                wmma::mma_sync(acc[i][j], af, bf[j], acc[i][j]);
        }
    }

    #pragma unroll
    for (int i = 0; i < 2; i++) {
        #pragma unroll
        for (int j = 0; j < 4; j++) {
            int gr0 = rowBase + wr * 32 + i * 16;
            int gc0 = colBase + wc * 64 + j * 16;
            if (gr0 >= M || gc0 >= Nc) continue;
            if (gr0 + 15 < M && gc0 + 15 < Nc) {
                wmma::store_matrix_sync(C + (size_t)gr0 * Nc + gc0, acc[i][j], Nc, wmma::mem_row_major);
            } else {
                wmma::store_matrix_sync(scr[wid], acc[i][j], 20, wmma::mem_row_major);
                __syncwarp();
                for (int e = lane; e < 256; e += 32) {
                    int r = e >> 4, c = e & 15;
                    if (gr0 + r < M && gc0 + c < Nc)
                        C[(size_t)(gr0 + r) * Nc + gc0 + c] = scr[wid][r * 20 + c];
                }
                __syncwarp();
            }
        }
    }
}

// ---------------- pure CSR gather + self-loop (no bias/LN) ----------------
// out[row] = sum_e coef*h[src] + dinv[row]^2 * h[row].  One warp per node, F=128.
__global__ void gather_kernel(const float* __restrict__ h,
                              const float* __restrict__ dinv,
                              const int* __restrict__ rowptr,
                              const int2* __restrict__ csr,
                              float* __restrict__ out, int n)
{
    int row = (blockIdx.x * blockDim.x + threadIdx.x) >> 5;
    int lane = threadIdx.x & 31;
    if (row >= n) return;

    float4 acc;
    {
        float dv = dinv[row];
        float d2 = dv * dv;
        float4 t = ((const float4*)(h + (size_t)row * 128))[lane];
        acc.x = t.x * d2; acc.y = t.y * d2; acc.z = t.z * d2; acc.w = t.w * d2;
    }

    int e = rowptr[row];
    int e1 = rowptr[row + 1];
    for (; e + 1 < e1; e += 2) {
        int2 c0 = csr[e];
        int2 c1 = csr[e + 1];
        float w0 = __int_as_float(c0.y);
        float w1 = __int_as_float(c1.y);
        float4 t0 = ((const float4*)(h + (size_t)c0.x * 128))[lane];
        float4 t1 = ((const float4*)(h + (size_t)c1.x * 128))[lane];
        acc.x += t0.x * w0 + t1.x * w1;
        acc.y += t0.y * w0 + t1.y * w1;
        acc.z += t0.z * w0 + t1.z * w1;
        acc.w += t0.w * w0 + t1.w * w1;
    }
    if (e < e1) {
        int2 c0 = csr[e];
        float w0 = __int_as_float(c0.y);
        float4 t0 = ((const float4*)(h + (size_t)c0.x * 128))[lane];
        acc.x += t0.x * w0;
        acc.y += t0.y * w0;
        acc.z += t0.z * w0;
        acc.w += t0.w * w0;
    }
    ((float4*)(out + (size_t)row * 128))[lane] = acc;
}

// ---------------- fused CSR gather + self-loop + bias + LayerNorm + ELU (F=128) ----------------
__global__ void gather_ln_elu_kernel(const float* __restrict__ h,
                                     const float* __restrict__ dinv,
                                     const int* __restrict__ rowptr,
                                     const int2* __restrict__ csr,
                                     const float* __restrict__ bias,
                                     const float* __restrict__ g,
                                     const float* __restrict__ be,
                                     float* __restrict__ out, int n)
{
    int row = (blockIdx.x * blockDim.x + threadIdx.x) >> 5;
    int lane = threadIdx.x & 31;
    if (row >= n) return;

    float4 acc;
    {
        float dv = dinv[row];
        float d2 = dv * dv;
        float4 t = ((const float4*)(h + (size_t)row * 128))[lane];
        acc.x = t.x * d2; acc.y = t.y * d2; acc.z = t.z * d2; acc.w = t.w * d2;
    }

    int e = rowptr[row];
    int e1 = rowptr[row + 1];
    for (; e + 1 < e1; e += 2) {
        int2 c0 = csr[e];
        int2 c1 = csr[e + 1];
        float w0 = __int_as_float(c0.y);
        float w1 = __int_as_float(c1.y);
        float4 t0 = ((const float4*)(h + (size_t)c0.x * 128))[lane];
        float4 t1 = ((const float4*)(h + (size_t)c1.x * 128))[lane];
        acc.x += t0.x * w0 + t1.x * w1;
        acc.y += t0.y * w0 + t1.y * w1;
        acc.z += t0.z * w0 + t1.z * w1;
        acc.w += t0.w * w0 + t1.w * w1;
    }
    if (e < e1) {
        int2 c0 = csr[e];
        float w0 = __int_as_float(c0.y);
        float4 t0 = ((const float4*)(h + (size_t)c0.x * 128))[lane];
        acc.x += t0.x * w0;
        acc.y += t0.y * w0;
        acc.z += t0.z * w0;
        acc.w += t0.w * w0;
    }

    {
        float4 b4 = ((const float4*)bias)[lane];
        acc.x += b4.x; acc.y += b4.y; acc.z += b4.z; acc.w += b4.w;
    }

    float sum = acc.x + acc.y + acc.z + acc.w;
    #pragma unroll
    for (int o = 16; o > 0; o >>= 1) sum += __shfl_xor_sync(0xFFFFFFFFu, sum, o);
    float mu = sum * (1.0f / 128.0f);
    float dx = acc.x - mu, dy = acc.y - mu, dz = acc.z - mu, dw = acc.w - mu;
    float vsum = dx * dx + dy * dy + dz * dz + dw * dw;
    #pragma unroll
    for (int o = 16; o > 0; o >>= 1) vsum += __shfl_xor_sync(0xFFFFFFFFu, vsum, o);
    float rstd = rsqrtf(vsum * (1.0f / 128.0f) + EPS);

    float4 g4 = ((const float4*)g)[lane];
    float4 b4 = ((const float4*)be)[lane];
    float4 r;
    float y;
    y = dx * rstd * g4.x + b4.x; r.x = (y > 0.f) ? y : expm1f(y);
    y = dy * rstd * g4.y + b4.y; r.y = (y > 0.f) ? y : expm1f(y);
    y = dz * rstd * g4.z + b4.z; r.z = (y > 0.f) ? y : expm1f(y);
    y = dw * rstd * g4.w + b4.w; r.w = (y > 0.f) ? y : expm1f(y);
    ((float4*)(out + (size_t)row * 128))[lane] = r;
}

// ---------------- standalone LayerNorm + ELU (F = 64 or 256) ----------------
__global__ void ln_elu_kernel(float* __restrict__ h, const float* __restrict__ g,
                              const float* __restrict__ b, int n, int F)
{
    int row = (blockIdx.x * blockDim.x + threadIdx.x) >> 5;
    int lane = threadIdx.x & 31;
    if (row >= n) return;
    float* hr = h + (size_t)row * F;
    int per = F >> 5;
    float vals[8];
    float sum = 0.0f;
    for (int i = 0; i < per; i++) {
        vals[i] = hr[lane + 32 * i];
        sum += vals[i];
    }
    #pragma unroll
    for (int o = 16; o > 0; o >>= 1) sum += __shfl_xor_sync(0xFFFFFFFFu, sum, o);
    float mu = sum / (float)F;
    float vsum = 0.0f;
    for (int i = 0; i < per; i++) {
        float dv = vals[i] - mu;
        vsum += dv * dv;
    }
    #pragma unroll
    for (int o = 16; o > 0; o >>= 1) vsum += __shfl_xor_sync(0xFFFFFFFFu, vsum, o);
    float rstd = rsqrtf(vsum / (float)F + EPS);
    for (int i = 0; i < per; i++) {
        int f = lane + 32 * i;
        float y = (vals[i] - mu) * rstd * g[f] + b[f];
        hr[f] = (y > 0.0f) ? y : expm1f(y);
    }
}

// ---------------- host ----------------
extern "C" void kernel_launch(void* const* d_in, const int* in_sizes, int n_in,
                              void* d_out, int out_size)
{
    const float* x    = (const float*)d_in[0];
    const int* eidx   = (const int*)d_in[1];
    const float* W1   = (const float*)d_in[2];
    const float* b1   = (const float*)d_in[3];
    const float* g1   = (const float*)d_in[4];
    const float* be1  = (const float*)d_in[5];
    const float* W2   = (const float*)d_in[6];
    const float* b2   = (const float*)d_in[7];
    const float* g2   = (const float*)d_in[8];
    const float* be2  = (const float*)d_in[9];
    const float* W3   = (const float*)d_in[10];
    const float* b3   = (const float*)d_in[11];
    const float* g3   = (const float*)d_in[12];
    const float* be3  = (const float*)d_in[13];
    const float* Wl1  = (const float*)d_in[14];
    const float* bl1  = (const float*)d_in[15];
    const float* g4   = (const float*)d_in[16];
    const float* be4  = (const float*)d_in[17];
    const float* Wl2  = (const float*)d_in[18];
    const float* bl2  = (const float*)d_in[19];
    float* out = (float*)d_out;

    const int N = in_sizes[0] / 128;      // 50000
    const int E = in_sizes[1] / 2;        // 800000
    const int H = 128, H2 = 256, HL = 64, OUT = 500;

    const int* src = eidx;
    const int* dst = eidx + E;

    float *bufA, *bufB, *dinv;
    int *deg, *rowptr, *cursor, *incl, *bsums;
    int2* csr;
    cudaGetSymbolAddress((void**)&bufA, g_bufA);
    cudaGetSymbolAddress((void**)&bufB, g_bufB);
    cudaGetSymbolAddress((void**)&dinv, g_dinv);
    cudaGetSymbolAddress((void**)&deg, g_deg);
    cudaGetSymbolAddress((void**)&rowptr, g_rowptr);
    cudaGetSymbolAddress((void**)&cursor, g_cursor);
    cudaGetSymbolAddress((void**)&csr, g_csr);
    cudaGetSymbolAddress((void**)&incl, g_incl);
    cudaGetSymbolAddress((void**)&bsums, g_bsums);

    // ---- build dinv + CSR (by dst) ----
    zero_deg_kernel<<<(N + 255) / 256, 256>>>(deg, N);
    count_deg_kernel<<<(E + 255) / 256, 256>>>(dst, deg, E);
    dinv_kernel<<<(N + 255) / 256, 256>>>(deg, dinv, N);
    int nb = (N + 1023) / 1024;
    scan_partial_kernel<<<nb, 1024>>>(deg, incl, bsums, N);
    scan_bsums_kernel<<<1, 32>>>(bsums, nb);
    scan_finalize_kernel<<<(N + 255) / 256, 256>>>(deg, incl, bsums, rowptr, cursor, N);
    fill_csr_kernel<<<(E + 255) / 256, 256>>>(src, dst, dinv, cursor, csr, E);

    auto gemmGrid = [](int M, int Nc) { return dim3((Nc + 127) / 128, (M + 127) / 128); };
    int warpBlocks = (N + 7) / 8;

    // --- GCN layer 1: h1 = LN/ELU( Â(x W1) + b1 ) ---
    gemm_tf32_kernel<<<gemmGrid(N, H), 256>>>(x, W1, nullptr, bufA, N, 128, H, 0);
    gather_ln_elu_kernel<<<warpBlocks, 256>>>(bufA, dinv, rowptr, csr, b1, g1, be1, bufB, N);

    // --- GCN layer 2 (reordered): h2 = LN/ELU( (Â h1) W2 + b2 ) ---
    gather_kernel<<<warpBlocks, 256>>>(bufB, dinv, rowptr, csr, bufA, N);
    gemm_tf32_kernel<<<gemmGrid(N, H2), 256>>>(bufA, W2, b2, bufB, N, H, H2, 1);
    ln_elu_kernel<<<warpBlocks, 256>>>(bufB, g2, be2, N, H2);

    // --- GCN layer 3: h3 = LN/ELU( Â(h2 W3) + b3 ) ---
    gemm_tf32_kernel<<<gemmGrid(N, H), 256>>>(bufB, W3, nullptr, bufA, N, H2, H, 0);
    gather_ln_elu_kernel<<<warpBlocks, 256>>>(bufA, dinv, rowptr, csr, b3, g3, be3, bufB, N);

    // --- Linear 128 -> 64, LN, ELU ---
    gemm_tf32_kernel<<<gemmGrid(N, HL), 256>>>(bufB, Wl1, bl1, bufA, N, H, HL, 1);
    ln_elu_kernel<<<warpBlocks, 256>>>(bufA, g4, be4, N, HL);

    // --- Linear 64 -> 500 (output) ---
    gemm_tf32_kernel<<<gemmGrid(N, OUT), 256>>>(bufA, Wl2, bl2, out, N, HL, OUT, 1);

    (void)n_in; (void)out_size;
}

// round 10
// speedup vs baseline: 1.0690x; 1.0690x over previous
#include <cuda_runtime.h>
#include <mma.h>
#include <math.h>

using namespace nvcuda;

#define NNODES 50000
#define NEDGES 800000
#define MAXF   256
#define EPS    1e-5f

// ---------------- device scratch (no allocations allowed) ----------------
__device__ float g_bufA[(size_t)NNODES * MAXF];
__device__ float g_bufB[(size_t)NNODES * MAXF];
__device__ float g_dinv[NNODES];
__device__ int   g_deg[NNODES];
__device__ int   g_rowptr[NNODES + 1];
__device__ int   g_cursor[NNODES];
__device__ int2  g_csr[NEDGES];          // {src, coef-as-int-bits}
__device__ int   g_incl[NNODES];
__device__ int   g_bsums[64];

// ---------------- degree / dinv ----------------
__global__ void zero_deg_kernel(int* deg, int n) {
    int i = blockIdx.x * blockDim.x + threadIdx.x;
    if (i < n) deg[i] = 0;
}

__global__ void count_deg_kernel(const int* __restrict__ dst, int* deg, int E) {
    int i = blockIdx.x * blockDim.x + threadIdx.x;
    if (i < E) atomicAdd(&deg[dst[i]], 1);
}

__global__ void dinv_kernel(const int* __restrict__ deg, float* dinv, int n) {
    int i = blockIdx.x * blockDim.x + threadIdx.x;
    if (i < n) dinv[i] = rsqrtf((float)deg[i] + 1.0f);
}

// ---------------- multi-block scan (3 stages) ----------------
__global__ void scan_partial_kernel(const int* __restrict__ deg, int* incl, int* bsums, int n)
{
    __shared__ int warpsums[32];
    int i = blockIdx.x * 1024 + threadIdx.x;
    int lane = threadIdx.x & 31;
    int wid = threadIdx.x >> 5;
    int v = (i < n) ? deg[i] : 0;
    int x = v;
    #pragma unroll
    for (int o = 1; o < 32; o <<= 1) {
        int t = __shfl_up_sync(0xFFFFFFFFu, x, o);
        if (lane >= o) x += t;
    }
    if (lane == 31) warpsums[wid] = x;
    __syncthreads();
    if (wid == 0) {
        int s = warpsums[lane];
        #pragma unroll
        for (int o = 1; o < 32; o <<= 1) {
            int t = __shfl_up_sync(0xFFFFFFFFu, s, o);
            if (lane >= o) s += t;
        }
        warpsums[lane] = s;
    }
    __syncthreads();
    int inclv = x + (wid > 0 ? warpsums[wid - 1] : 0);
    if (i < n) incl[i] = inclv;
    if (threadIdx.x == 1023) bsums[blockIdx.x] = inclv;
}

__global__ void scan_bsums_kernel(int* bsums, int nb)
{
    if (threadIdx.x == 0) {
        int run = 0;
        for (int b = 0; b < nb; b++) {
            int t = bsums[b];
            bsums[b] = run;
            run += t;
        }
    }
}

__global__ void scan_finalize_kernel(const int* __restrict__ deg, const int* __restrict__ incl,
                                     const int* __restrict__ bsums,
                                     int* rowptr, int* cursor, int n)
{
    int i = blockIdx.x * blockDim.x + threadIdx.x;
    if (i >= n) return;
    int val = bsums[i >> 10] + incl[i];
    rowptr[i + 1] = val;
    cursor[i] = val - deg[i];
    if (i == 0) rowptr[0] = 0;
}

// ---------------- CSR fill (packed int2) ----------------
__global__ void fill_csr_kernel(const int* __restrict__ src, const int* __restrict__ dst,
                                const float* __restrict__ dinv, int* cursor,
                                int2* csr, int E)
{
    int e = blockIdx.x * blockDim.x + threadIdx.x;
    if (e >= E) return;
    int s = src[e];
    int d = dst[e];
    int p = atomicAdd(&cursor[d], 1);
    csr[p] = make_int2(s, __float_as_int(dinv[s] * dinv[d]));
}

// ---------------- generic TF32 wmma GEMM: C = A @ W (+bias) ----------------
#define LDT 132

__global__ __launch_bounds__(256)
void gemm_tf32_kernel(const float* __restrict__ A, const float* __restrict__ W,
                      const float* __restrict__ bias, float* __restrict__ C,
                      int M, int K, int Nc, int addBias)
{
    __shared__ __align__(16) float As[16][LDT];
    __shared__ __align__(16) float Ws[16][LDT];
    __shared__ __align__(16) float scr[8][16 * 20];

    const int tid = threadIdx.x;
    const int wid = tid >> 5;
    const int lane = tid & 31;
    const int wr = wid >> 1;
    const int wc = wid & 1;
    const int rowBase = blockIdx.y * 128;
    const int colBase = blockIdx.x * 128;

    wmma::fragment<wmma::accumulator, 16, 16, 8, float> acc[2][4];
    #pragma unroll
    for (int i = 0; i < 2; i++)
        #pragma unroll
        for (int j = 0; j < 4; j++) wmma::fill_fragment(acc[i][j], 0.0f);

    for (int k0 = 0; k0 < K; k0 += 16) {
        #pragma unroll
        for (int t = 0; t < 2; t++) {
            int lin = t * 256 + tid;
            int r = lin >> 2;
            int c4 = lin & 3;
            float4 v = make_float4(0.f, 0.f, 0.f, 0.f);
            int gr = rowBase + r;
            if (gr < M)
                v = *(const float4*)(A + (size_t)gr * K + k0 + 4 * c4);
            As[4 * c4 + 0][r] = wmma::__float_to_tf32(v.x);
            As[4 * c4 + 1][r] = wmma::__float_to_tf32(v.y);
            As[4 * c4 + 2][r] = wmma::__float_to_tf32(v.z);
            As[4 * c4 + 3][r] = wmma::__float_to_tf32(v.w);
        }
        #pragma unroll
        for (int t = 0; t < 2; t++) {
            int lin = t * 256 + tid;
            int r = lin >> 5;
            int c4 = lin & 31;
            float4 v = make_float4(0.f, 0.f, 0.f, 0.f);
            int gc = colBase + 4 * c4;
            if (gc + 3 < Nc)
                v = *(const float4*)(W + (size_t)(k0 + r) * Nc + gc);
            v.x = wmma::__float_to_tf32(v.x);
            v.y = wmma::__float_to_tf32(v.y);
            v.z = wmma::__float_to_tf32(v.z);
            v.w = wmma::__float_to_tf32(v.w);
            *(float4*)&Ws[r][4 * c4] = v;
        }
        __syncthreads();

        #pragma unroll
        for (int ks = 0; ks < 16; ks += 8) {
            wmma::fragment<wmma::matrix_a, 16, 16, 8, wmma::precision::tf32, wmma::col_major> af[2];
            wmma::fragment<wmma::matrix_b, 16, 16, 8, wmma::precision::tf32, wmma::row_major> bf[4];
            #pragma unroll
            for (int i = 0; i < 2; i++)
                wmma::load_matrix_sync(af[i], &As[ks][wr * 32 + i * 16], LDT);
            #pragma unroll
            for (int j = 0; j < 4; j++)
                wmma::load_matrix_sync(bf[j], &Ws[ks][wc * 64 + j * 16], LDT);
            #pragma unroll
            for (int i = 0; i < 2; i++)
                #pragma unroll
                for (int j = 0; j < 4; j++)
                    wmma::mma_sync(acc[i][j], af[i], bf[j], acc[i][j]);
        }
        __syncthreads();
    }

    if (addBias) {
        for (int idx = tid; idx < 8 * LDT; idx += 256) {
            int k = idx / LDT;
            int m = idx % LDT;
            As[k][m] = (k == 0 && m < 128) ? 1.0f : 0.0f;
            float bv = 0.0f;
            if (k == 0 && m < 128 && colBase + m < Nc) bv = bias[colBase + m];
            Ws[k][m] = wmma::__float_to_tf32(bv);
        }
        __syncthreads();
        wmma::fragment<wmma::matrix_a, 16, 16, 8, wmma::precision::tf32, wmma::col_major> af;
        wmma::fragment<wmma::matrix_b, 16, 16, 8, wmma::precision::tf32, wmma::row_major> bf[4];
        #pragma unroll
        for (int j = 0; j < 4; j++)
            wmma::load_matrix_sync(bf[j], &Ws[0][wc * 64 + j * 16], LDT);
        #pragma unroll
        for (int i = 0; i < 2; i++) {
            wmma::load_matrix_sync(af, &As[0][wr * 32 + i * 16], LDT);
            #pragma unroll
            for (int j = 0; j < 4; j++)
                wmma::mma_sync(acc[i][j], af, bf[j], acc[i][j]);
        }
    }

    #pragma unroll
    for (int i = 0; i < 2; i++) {
        #pragma unroll
        for (int j = 0; j < 4; j++) {
            int gr0 = rowBase + wr * 32 + i * 16;
            int gc0 = colBase + wc * 64 + j * 16;
            if (gr0 >= M || gc0 >= Nc) continue;
            if (gr0 + 15 < M && gc0 + 15 < Nc) {
                wmma::store_matrix_sync(C + (size_t)gr0 * Nc + gc0, acc[i][j], Nc, wmma::mem_row_major);
            } else {
                wmma::store_matrix_sync(scr[wid], acc[i][j], 20, wmma::mem_row_major);
                __syncwarp();
                for (int e = lane; e < 256; e += 32) {
                    int r = e >> 4, c = e & 15;
                    if (gr0 + r < M && gc0 + c < Nc)
                        C[(size_t)(gr0 + r) * Nc + gc0 + c] = scr[wid][r * 20 + c];
                }
                __syncwarp();
            }
        }
    }
}

// ---------------- layer-2 fused GEMM + bias + LN + ELU ----------------
// C[M,256] = LN_ELU( A[M,128] @ W[128,256] + bias ). Block = 64 rows x 256 cols.
// 8 warps: wr = wid>>2 (2 row groups of 32), wc = wid&3 (4 col groups of 64).
// Dynamic smem: tiles (As 16x68, Ws 16x260) reused as 64x260 stage in epilogue.
#define LDA2 68
#define LDW2 260

__global__ __launch_bounds__(256)
void gemm_ln_tf32_kernel(const float* __restrict__ A, const float* __restrict__ W,
                         const float* __restrict__ bias,
                         const float* __restrict__ gam, const float* __restrict__ bet,
                         float* __restrict__ C, int M)
{
    extern __shared__ float smem[];
    float* Asm = smem;                 // [16][LDA2]
    float* Wsm = smem + 16 * LDA2;     // [16][LDW2]
    float* stage = smem;               // [64][LDW2] (reused after mainloop)

    const int K = 128, Nc = 256;
    const int tid = threadIdx.x;
    const int wid = tid >> 5;
    const int lane = tid & 31;
    const int wr = wid >> 2;           // 0..1
    const int wc = wid & 3;            // 0..3
    const int rowBase = blockIdx.x * 64;

    wmma::fragment<wmma::accumulator, 16, 16, 8, float> acc[2][4];
    #pragma unroll
    for (int i = 0; i < 2; i++)
        #pragma unroll
        for (int j = 0; j < 4; j++) wmma::fill_fragment(acc[i][j], 0.0f);

    for (int k0 = 0; k0 < K; k0 += 16) {
        // A tile: 64 rows x 16 k -> Asm[k][m], 256 float4, 1 per thread
        {
            int r = tid >> 2;           // 0..63
            int c4 = tid & 3;
            float4 v = make_float4(0.f, 0.f, 0.f, 0.f);
            int gr = rowBase + r;
            if (gr < M)
                v = *(const float4*)(A + (size_t)gr * K + k0 + 4 * c4);
            Asm[(4 * c4 + 0) * LDA2 + r] = wmma::__float_to_tf32(v.x);
            Asm[(4 * c4 + 1) * LDA2 + r] = wmma::__float_to_tf32(v.y);
            Asm[(4 * c4 + 2) * LDA2 + r] = wmma::__float_to_tf32(v.z);
            Asm[(4 * c4 + 3) * LDA2 + r] = wmma::__float_to_tf32(v.w);
        }
        // W tile: 16 k x 256 n, 1024 float4, 4 per thread
        #pragma unroll
        for (int t = 0; t < 4; t++) {
            int lin = t * 256 + tid;    // 0..1023
            int r = lin >> 6;           // 0..15
            int c4 = lin & 63;
            float4 v = *(const float4*)(W + (size_t)(k0 + r) * Nc + 4 * c4);
            v.x = wmma::__float_to_tf32(v.x);
            v.y = wmma::__float_to_tf32(v.y);
            v.z = wmma::__float_to_tf32(v.z);
            v.w = wmma::__float_to_tf32(v.w);
            *(float4*)&Wsm[r * LDW2 + 4 * c4] = v;
        }
        __syncthreads();

        #pragma unroll
        for (int ks = 0; ks < 16; ks += 8) {
            wmma::fragment<wmma::matrix_a, 16, 16, 8, wmma::precision::tf32, wmma::col_major> af[2];
            wmma::fragment<wmma::matrix_b, 16, 16, 8, wmma::precision::tf32, wmma::row_major> bf[4];
            #pragma unroll
            for (int i = 0; i < 2; i++)
                wmma::load_matrix_sync(af[i], &Asm[ks * LDA2 + wr * 32 + i * 16], LDA2);
            #pragma unroll
            for (int j = 0; j < 4; j++)
                wmma::load_matrix_sync(bf[j], &Wsm[ks * LDW2 + wc * 64 + j * 16], LDW2);
            #pragma unroll
            for (int i = 0; i < 2; i++)
                #pragma unroll
                for (int j = 0; j < 4; j++)
                    wmma::mma_sync(acc[i][j], af[i], bf[j], acc[i][j]);
        }
        __syncthreads();
    }

    // stage accumulators to smem (overwrites tiles; all warps past mainloop)
    #pragma unroll
    for (int i = 0; i < 2; i++)
        #pragma unroll
        for (int j = 0; j < 4; j++)
            wmma::store_matrix_sync(&stage[(wr * 32 + i * 16) * LDW2 + wc * 64 + j * 16],
                                    acc[i][j], LDW2, wmma::mem_row_major);
    __syncthreads();

    // epilogue: each warp LNs 8 rows. lane covers cols lane*4 and 128+lane*4.
    float4 ba = ((const float4*)bias)[lane];
    float4 bb = ((const float4*)bias)[32 + lane];
    float4 ga = ((const float4*)gam)[lane];
    float4 gb = ((const float4*)gam)[32 + lane];
    float4 ea = ((const float4*)bet)[lane];
    float4 eb = ((const float4*)bet)[32 + lane];

    #pragma unroll
    for (int rr = 0; rr < 8; rr++) {
        int r = wid * 8 + rr;
        int gr = rowBase + r;
        if (gr >= M) continue;
        float4 a = *(float4*)&stage[r * LDW2 + lane * 4];
        float4 b = *(float4*)&stage[r * LDW2 + 128 + lane * 4];
        a.x += ba.x; a.y += ba.y; a.z += ba.z; a.w += ba.w;
        b.x += bb.x; b.y += bb.y; b.z += bb.z; b.w += bb.w;

        float sum = a.x + a.y + a.z + a.w + b.x + b.y + b.z + b.w;
        #pragma unroll
        for (int o = 16; o > 0; o >>= 1) sum += __shfl_xor_sync(0xFFFFFFFFu, sum, o);
        float mu = sum * (1.0f / 256.0f);
        float d0 = a.x - mu, d1 = a.y - mu, d2 = a.z - mu, d3 = a.w - mu;
        float d4 = b.x - mu, d5 = b.y - mu, d6 = b.z - mu, d7 = b.w - mu;
        float vs = d0 * d0 + d1 * d1 + d2 * d2 + d3 * d3
                 + d4 * d4 + d5 * d5 + d6 * d6 + d7 * d7;
        #pragma unroll
        for (int o = 16; o > 0; o >>= 1) vs += __shfl_xor_sync(0xFFFFFFFFu, vs, o);
        float rstd = rsqrtf(vs * (1.0f / 256.0f) + EPS);

        float4 r0, r1;
        float y;
        y = d0 * rstd * ga.x + ea.x; r0.x = (y > 0.f) ? y : expm1f(y);
        y = d1 * rstd * ga.y + ea.y; r0.y = (y > 0.f) ? y : expm1f(y);
        y = d2 * rstd * ga.z + ea.z; r0.z = (y > 0.f) ? y : expm1f(y);
        y = d3 * rstd * ga.w + ea.w; r0.w = (y > 0.f) ? y : expm1f(y);
        y = d4 * rstd * gb.x + eb.x; r1.x = (y > 0.f) ? y : expm1f(y);
        y = d5 * rstd * gb.y + eb.y; r1.y = (y > 0.f) ? y : expm1f(y);
        y = d6 * rstd * gb.z + eb.z; r1.z = (y > 0.f) ? y : expm1f(y);
        y = d7 * rstd * gb.w + eb.w; r1.w = (y > 0.f) ? y : expm1f(y);
        *(float4*)(C + (size_t)gr * 256 + lane * 4) = r0;
        *(float4*)(C + (size_t)gr * 256 + 128 + lane * 4) = r1;
    }
}

// ---------------- pure CSR gather + self-loop, F=128, 4-way unrolled ----------------
__global__ void gather_kernel(const float* __restrict__ h,
                              const float* __restrict__ dinv,
                              const int* __restrict__ rowptr,
                              const int2* __restrict__ csr,
                              float* __restrict__ out, int n)
{
    int row = (blockIdx.x * blockDim.x + threadIdx.x) >> 5;
    int lane = threadIdx.x & 31;
    if (row >= n) return;

    float4 acc;
    {
        float dv = dinv[row];
        float d2 = dv * dv;
        float4 t = ((const float4*)(h + (size_t)row * 128))[lane];
        acc.x = t.x * d2; acc.y = t.y * d2; acc.z = t.z * d2; acc.w = t.w * d2;
    }

    int e = rowptr[row];
    int e1 = rowptr[row + 1];
    for (; e + 3 < e1; e += 4) {
        int2 c0 = csr[e], c1 = csr[e + 1], c2 = csr[e + 2], c3 = csr[e + 3];
        float4 t0 = ((const float4*)(h + (size_t)c0.x * 128))[lane];
        float4 t1 = ((const float4*)(h + (size_t)c1.x * 128))[lane];
        float4 t2 = ((const float4*)(h + (size_t)c2.x * 128))[lane];
        float4 t3 = ((const float4*)(h + (size_t)c3.x * 128))[lane];
        float w0 = __int_as_float(c0.y), w1 = __int_as_float(c1.y);
        float w2 = __int_as_float(c2.y), w3 = __int_as_float(c3.y);
        acc.x += t0.x * w0 + t1.x * w1 + t2.x * w2 + t3.x * w3;
        acc.y += t0.y * w0 + t1.y * w1 + t2.y * w2 + t3.y * w3;
        acc.z += t0.z * w0 + t1.z * w1 + t2.z * w2 + t3.z * w3;
        acc.w += t0.w * w0 + t1.w * w1 + t2.w * w2 + t3.w * w3;
    }
    for (; e < e1; e++) {
        int2 c0 = csr[e];
        float w0 = __int_as_float(c0.y);
        float4 t0 = ((const float4*)(h + (size_t)c0.x * 128))[lane];
        acc.x += t0.x * w0; acc.y += t0.y * w0;
        acc.z += t0.z * w0; acc.w += t0.w * w0;
    }
    ((float4*)(out + (size_t)row * 128))[lane] = acc;
}

// ---------------- fused CSR gather + bias + LN + ELU, F=128, 4-way unrolled ----------------
__global__ void gather_ln_elu_kernel(const float* __restrict__ h,
                                     const float* __restrict__ dinv,
                                     const int* __restrict__ rowptr,
                                     const int2* __restrict__ csr,
                                     const float* __restrict__ bias,
                                     const float* __restrict__ g,
                                     const float* __restrict__ be,
                                     float* __restrict__ out, int n)
{
    int row = (blockIdx.x * blockDim.x + threadIdx.x) >> 5;
    int lane = threadIdx.x & 31;
    if (row >= n) return;

    float4 acc;
    {
        float dv = dinv[row];
        float d2 = dv * dv;
        float4 t = ((const float4*)(h + (size_t)row * 128))[lane];
        acc.x = t.x * d2; acc.y = t.y * d2; acc.z = t.z * d2; acc.w = t.w * d2;
    }

    int e = rowptr[row];
    int e1 = rowptr[row + 1];
    for (; e + 3 < e1; e += 4) {
        int2 c0 = csr[e], c1 = csr[e + 1], c2 = csr[e + 2], c3 = csr[e + 3];
        float4 t0 = ((const float4*)(h + (size_t)c0.x * 128))[lane];
        float4 t1 = ((const float4*)(h + (size_t)c1.x * 128))[lane];
        float4 t2 = ((const float4*)(h + (size_t)c2.x * 128))[lane];
        float4 t3 = ((const float4*)(h + (size_t)c3.x * 128))[lane];
        float w0 = __int_as_float(c0.y), w1 = __int_as_float(c1.y);
        float w2 = __int_as_float(c2.y), w3 = __int_as_float(c3.y);
        acc.x += t0.x * w0 + t1.x * w1 + t2.x * w2 + t3.x * w3;
        acc.y += t0.y * w0 + t1.y * w1 + t2.y * w2 + t3.y * w3;
        acc.z += t0.z * w0 + t1.z * w1 + t2.z * w2 + t3.z * w3;
        acc.w += t0.w * w0 + t1.w * w1 + t2.w * w2 + t3.w * w3;
    }
    for (; e < e1; e++) {
        int2 c0 = csr[e];
        float w0 = __int_as_float(c0.y);
        float4 t0 = ((const float4*)(h + (size_t)c0.x * 128))[lane];
        acc.x += t0.x * w0; acc.y += t0.y * w0;
        acc.z += t0.z * w0; acc.w += t0.w * w0;
    }

    {
        float4 b4 = ((const float4*)bias)[lane];
        acc.x += b4.x; acc.y += b4.y; acc.z += b4.z; acc.w += b4.w;
    }

    float sum = acc.x + acc.y + acc.z + acc.w;
    #pragma unroll
    for (int o = 16; o > 0; o >>= 1) sum += __shfl_xor_sync(0xFFFFFFFFu, sum, o);
    float mu = sum * (1.0f / 128.0f);
    float dx = acc.x - mu, dy = acc.y - mu, dz = acc.z - mu, dw = acc.w - mu;
    float vsum = dx * dx + dy * dy + dz * dz + dw * dw;
    #pragma unroll
    for (int o = 16; o > 0; o >>= 1) vsum += __shfl_xor_sync(0xFFFFFFFFu, vsum, o);
    float rstd = rsqrtf(vsum * (1.0f / 128.0f) + EPS);

    float4 g4 = ((const float4*)g)[lane];
    float4 b4 = ((const float4*)be)[lane];
    float4 r;
    float y;
    y = dx * rstd * g4.x + b4.x; r.x = (y > 0.f) ? y : expm1f(y);
    y = dy * rstd * g4.y + b4.y; r.y = (y > 0.f) ? y : expm1f(y);
    y = dz * rstd * g4.z + b4.z; r.z = (y > 0.f) ? y : expm1f(y);
    y = dw * rstd * g4.w + b4.w; r.w = (y > 0.f) ? y : expm1f(y);
    ((float4*)(out + (size_t)row * 128))[lane] = r;
}

// ---------------- LayerNorm + ELU for F=64 (float2 per lane) ----------------
__global__ void ln_elu64_kernel(float* __restrict__ h, const float* __restrict__ g,
                                const float* __restrict__ b, int n)
{
    int row = (blockIdx.x * blockDim.x + threadIdx.x) >> 5;
    int lane = threadIdx.x & 31;
    if (row >= n) return;
    float2 v = ((float2*)(h + (size_t)row * 64))[lane];
    float sum = v.x + v.y;
    #pragma unroll
    for (int o = 16; o > 0; o >>= 1) sum += __shfl_xor_sync(0xFFFFFFFFu, sum, o);
    float mu = sum * (1.0f / 64.0f);
    float dx = v.x - mu, dy = v.y - mu;
    float vs = dx * dx + dy * dy;
    #pragma unroll
    for (int o = 16; o > 0; o >>= 1) vs += __shfl_xor_sync(0xFFFFFFFFu, vs, o);
    float rstd = rsqrtf(vs * (1.0f / 64.0f) + EPS);
    float2 gg = ((const float2*)g)[lane];
    float2 bb = ((const float2*)b)[lane];
    float2 r;
    float y;
    y = dx * rstd * gg.x + bb.x; r.x = (y > 0.f) ? y : expm1f(y);
    y = dy * rstd * gg.y + bb.y; r.y = (y > 0.f) ? y : expm1f(y);
    ((float2*)(h + (size_t)row * 64))[lane] = r;
}

// ---------------- host ----------------
extern "C" void kernel_launch(void* const* d_in, const int* in_sizes, int n_in,
                              void* d_out, int out_size)
{
    const float* x    = (const float*)d_in[0];
    const int* eidx   = (const int*)d_in[1];
    const float* W1   = (const float*)d_in[2];
    const float* b1   = (const float*)d_in[3];
    const float* g1   = (const float*)d_in[4];
    const float* be1  = (const float*)d_in[5];
    const float* W2   = (const float*)d_in[6];
    const float* b2   = (const float*)d_in[7];
    const float* g2   = (const float*)d_in[8];
    const float* be2  = (const float*)d_in[9];
    const float* W3   = (const float*)d_in[10];
    const float* b3   = (const float*)d_in[11];
    const float* g3   = (const float*)d_in[12];
    const float* be3  = (const float*)d_in[13];
    const float* Wl1  = (const float*)d_in[14];
    const float* bl1  = (const float*)d_in[15];
    const float* g4   = (const float*)d_in[16];
    const float* be4  = (const float*)d_in[17];
    const float* Wl2  = (const float*)d_in[18];
    const float* bl2  = (const float*)d_in[19];
    float* out = (float*)d_out;

    const int N = in_sizes[0] / 128;      // 50000
    const int E = in_sizes[1] / 2;        // 800000
    const int H = 128, H2 = 256, HL = 64, OUT = 500;

    const int* src = eidx;
    const int* dst = eidx + E;

    float *bufA, *bufB, *dinv;
    int *deg, *rowptr, *cursor, *incl, *bsums;
    int2* csr;
    cudaGetSymbolAddress((void**)&bufA, g_bufA);
    cudaGetSymbolAddress((void**)&bufB, g_bufB);
    cudaGetSymbolAddress((void**)&dinv, g_dinv);
    cudaGetSymbolAddress((void**)&deg, g_deg);
    cudaGetSymbolAddress((void**)&rowptr, g_rowptr);
    cudaGetSymbolAddress((void**)&cursor, g_cursor);
    cudaGetSymbolAddress((void**)&csr, g_csr);
    cudaGetSymbolAddress((void**)&incl, g_incl);
    cudaGetSymbolAddress((void**)&bsums, g_bsums);

    // opt-in dynamic smem for the fused layer-2 GEMM (64 x 260 floats)
    static const int DYN_SMEM = 64 * 260 * (int)sizeof(float);   // 66560
    cudaFuncSetAttribute(gemm_ln_tf32_kernel,
                         cudaFuncAttributeMaxDynamicSharedMemorySize, DYN_SMEM);

    // ---- build dinv + CSR (by dst) ----
    zero_deg_kernel<<<(N + 255) / 256, 256>>>(deg, N);
    count_deg_kernel<<<(E + 255) / 256, 256>>>(dst, deg, E);
    dinv_kernel<<<(N + 255) / 256, 256>>>(deg, dinv, N);
    int nb = (N + 1023) / 1024;
    scan_partial_kernel<<<nb, 1024>>>(deg, incl, bsums, N);
    scan_bsums_kernel<<<1, 32>>>(bsums, nb);
    scan_finalize_kernel<<<(N + 255) / 256, 256>>>(deg, incl, bsums, rowptr, cursor, N);
    fill_csr_kernel<<<(E + 255) / 256, 256>>>(src, dst, dinv, cursor, csr, E);

    auto gemmGrid = [](int M, int Nc) { return dim3((Nc + 127) / 128, (M + 127) / 128); };
    int warpBlocks = (N + 7) / 8;

    // --- GCN layer 1: h1 = LN/ELU( Â(x W1) + b1 ) ---
    gemm_tf32_kernel<<<gemmGrid(N, H), 256>>>(x, W1, nullptr, bufA, N, 128, H, 0);
    gather_ln_elu_kernel<<<warpBlocks, 256>>>(bufA, dinv, rowptr, csr, b1, g1, be1, bufB, N);

    // --- GCN layer 2 (reordered + fused): h2 = LN/ELU( (Â h1) W2 + b2 ) ---
    gather_kernel<<<warpBlocks, 256>>>(bufB, dinv, rowptr, csr, bufA, N);
    gemm_ln_tf32_kernel<<<(N + 63) / 64, 256, DYN_SMEM>>>(bufA, W2, b2, g2, be2, bufB, N);

    // --- GCN layer 3: h3 = LN/ELU( Â(h2 W3) + b3 ) ---
    gemm_tf32_kernel<<<gemmGrid(N, H), 256>>>(bufB, W3, nullptr, bufA, N, H2, H, 0);
    gather_ln_elu_kernel<<<warpBlocks, 256>>>(bufA, dinv, rowptr, csr, b3, g3, be3, bufB, N);

    // --- Linear 128 -> 64, LN, ELU ---
    gemm_tf32_kernel<<<gemmGrid(N, HL), 256>>>(bufB, Wl1, bl1, bufA, N, H, HL, 1);
    ln_elu64_kernel<<<warpBlocks, 256>>>(bufA, g4, be4, N);

    // --- Linear 64 -> 500 (output) ---
    gemm_tf32_kernel<<<gemmGrid(N, OUT), 256>>>(bufA, Wl2, bl2, out, N, HL, OUT, 1);

    (void)n_in; (void)out_size;
}

// round 11
// speedup vs baseline: 1.1505x; 1.0762x over previous
#include <cuda_runtime.h>
#include <mma.h>
#include <math.h>

using namespace nvcuda;

#define NNODES 50000
#define NEDGES 800000
#define MAXF   256
#define EPS    1e-5f

// ---------------- device scratch (no allocations allowed) ----------------
__device__ float g_bufA[(size_t)NNODES * MAXF];
__device__ float g_bufB[(size_t)NNODES * MAXF];
__device__ float g_dinv[NNODES];
__device__ int   g_deg[NNODES];
__device__ int   g_rowptr[NNODES + 1];
__device__ int   g_cursor[NNODES];
__device__ int2  g_csr[NEDGES];          // {src, coef-as-int-bits}
__device__ int   g_incl[NNODES];
__device__ int   g_bsums[64];

// ---------------- degree / dinv ----------------
__global__ void zero_deg_kernel(int* deg, int n) {
    int i = blockIdx.x * blockDim.x + threadIdx.x;
    if (i < n) deg[i] = 0;
}

__global__ void count_deg_kernel(const int* __restrict__ dst, int* deg, int E) {
    int i = blockIdx.x * blockDim.x + threadIdx.x;
    if (i < E) atomicAdd(&deg[dst[i]], 1);
}

__global__ void dinv_kernel(const int* __restrict__ deg, float* dinv, int n) {
    int i = blockIdx.x * blockDim.x + threadIdx.x;
    if (i < n) dinv[i] = rsqrtf((float)deg[i] + 1.0f);
}

// ---------------- multi-block scan (3 stages) ----------------
__global__ void scan_partial_kernel(const int* __restrict__ deg, int* incl, int* bsums, int n)
{
    __shared__ int warpsums[32];
    int i = blockIdx.x * 1024 + threadIdx.x;
    int lane = threadIdx.x & 31;
    int wid = threadIdx.x >> 5;
    int v = (i < n) ? deg[i] : 0;
    int x = v;
    #pragma unroll
    for (int o = 1; o < 32; o <<= 1) {
        int t = __shfl_up_sync(0xFFFFFFFFu, x, o);
        if (lane >= o) x += t;
    }
    if (lane == 31) warpsums[wid] = x;
    __syncthreads();
    if (wid == 0) {
        int s = warpsums[lane];
        #pragma unroll
        for (int o = 1; o < 32; o <<= 1) {
            int t = __shfl_up_sync(0xFFFFFFFFu, s, o);
            if (lane >= o) s += t;
        }
        warpsums[lane] = s;
    }
    __syncthreads();
    int inclv = x + (wid > 0 ? warpsums[wid - 1] : 0);
    if (i < n) incl[i] = inclv;
    if (threadIdx.x == 1023) bsums[blockIdx.x] = inclv;
}

__global__ void scan_bsums_kernel(int* bsums, int nb)
{
    if (threadIdx.x == 0) {
        int run = 0;
        for (int b = 0; b < nb; b++) {
            int t = bsums[b];
            bsums[b] = run;
            run += t;
        }
    }
}

__global__ void scan_finalize_kernel(const int* __restrict__ deg, const int* __restrict__ incl,
                                     const int* __restrict__ bsums,
                                     int* rowptr, int* cursor, int n)
{
    int i = blockIdx.x * blockDim.x + threadIdx.x;
    if (i >= n) return;
    int val = bsums[i >> 10] + incl[i];
    rowptr[i + 1] = val;
    cursor[i] = val - deg[i];
    if (i == 0) rowptr[0] = 0;
}

// ---------------- CSR fill (packed int2) ----------------
__global__ void fill_csr_kernel(const int* __restrict__ src, const int* __restrict__ dst,
                                const float* __restrict__ dinv, int* cursor,
                                int2* csr, int E)
{
    int e = blockIdx.x * blockDim.x + threadIdx.x;
    if (e >= E) return;
    int s = src[e];
    int d = dst[e];
    int p = atomicAdd(&cursor[d], 1);
    csr[p] = make_int2(s, __float_as_int(dinv[s] * dinv[d]));
}

// ---------------- generic TF32 wmma GEMM, register double-buffered ----------------
#define LDT 132

__global__ __launch_bounds__(256)
void gemm_tf32_kernel(const float* __restrict__ A, const float* __restrict__ W,
                      const float* __restrict__ bias, float* __restrict__ C,
                      int M, int K, int Nc, int addBias)
{
    __shared__ __align__(16) float As[16][LDT];
    __shared__ __align__(16) float Ws[16][LDT];
    __shared__ __align__(16) float scr[8][16 * 20];

    const int tid = threadIdx.x;
    const int wid = tid >> 5;
    const int lane = tid & 31;
    const int wr = wid >> 1;
    const int wc = wid & 1;
    const int rowBase = blockIdx.y * 128;
    const int colBase = blockIdx.x * 128;

    // per-thread load coordinates
    const int arA[2] = { (0 * 256 + tid) >> 2, (1 * 256 + tid) >> 2 };
    const int acA = tid & 3;                   // same for both t
    const int wrW[2] = { (0 * 256 + tid) >> 5, (1 * 256 + tid) >> 5 };
    const int wcW = tid & 31;

    wmma::fragment<wmma::accumulator, 16, 16, 8, float> acc[2][4];
    #pragma unroll
    for (int i = 0; i < 2; i++)
        #pragma unroll
        for (int j = 0; j < 4; j++) wmma::fill_fragment(acc[i][j], 0.0f);

    // initial tile (k0 = 0) straight to smem
    #pragma unroll
    for (int t = 0; t < 2; t++) {
        int r = arA[t];
        float4 v = make_float4(0.f, 0.f, 0.f, 0.f);
        int gr = rowBase + r;
        if (gr < M) v = *(const float4*)(A + (size_t)gr * K + 4 * acA);
        As[4 * acA + 0][r] = wmma::__float_to_tf32(v.x);
        As[4 * acA + 1][r] = wmma::__float_to_tf32(v.y);
        As[4 * acA + 2][r] = wmma::__float_to_tf32(v.z);
        As[4 * acA + 3][r] = wmma::__float_to_tf32(v.w);
    }
    #pragma unroll
    for (int t = 0; t < 2; t++) {
        int r = wrW[t];
        float4 v = make_float4(0.f, 0.f, 0.f, 0.f);
        int gc = colBase + 4 * wcW;
        if (gc + 3 < Nc) v = *(const float4*)(W + (size_t)r * Nc + gc);
        v.x = wmma::__float_to_tf32(v.x);
        v.y = wmma::__float_to_tf32(v.y);
        v.z = wmma::__float_to_tf32(v.z);
        v.w = wmma::__float_to_tf32(v.w);
        *(float4*)&Ws[r][4 * wcW] = v;
    }

    for (int k0 = 0; k0 < K; k0 += 16) {
        __syncthreads();
        bool more = (k0 + 16) < K;
        float4 pa[2], pw[2];
        if (more) {
            #pragma unroll
            for (int t = 0; t < 2; t++) {
                int r = arA[t];
                pa[t] = make_float4(0.f, 0.f, 0.f, 0.f);
                int gr = rowBase + r;
                if (gr < M) pa[t] = *(const float4*)(A + (size_t)gr * K + k0 + 16 + 4 * acA);
            }
            #pragma unroll
            for (int t = 0; t < 2; t++) {
                int r = wrW[t];
                pw[t] = make_float4(0.f, 0.f, 0.f, 0.f);
                int gc = colBase + 4 * wcW;
                if (gc + 3 < Nc) pw[t] = *(const float4*)(W + (size_t)(k0 + 16 + r) * Nc + gc);
            }
        }

        #pragma unroll
        for (int ks = 0; ks < 16; ks += 8) {
            wmma::fragment<wmma::matrix_a, 16, 16, 8, wmma::precision::tf32, wmma::col_major> af[2];
            wmma::fragment<wmma::matrix_b, 16, 16, 8, wmma::precision::tf32, wmma::row_major> bf[4];
            #pragma unroll
            for (int i = 0; i < 2; i++)
                wmma::load_matrix_sync(af[i], &As[ks][wr * 32 + i * 16], LDT);
            #pragma unroll
            for (int j = 0; j < 4; j++)
                wmma::load_matrix_sync(bf[j], &Ws[ks][wc * 64 + j * 16], LDT);
            #pragma unroll
            for (int i = 0; i < 2; i++)
                #pragma unroll
                for (int j = 0; j < 4; j++)
                    wmma::mma_sync(acc[i][j], af[i], bf[j], acc[i][j]);
        }
        __syncthreads();

        if (more) {
            #pragma unroll
            for (int t = 0; t < 2; t++) {
                int r = arA[t];
                As[4 * acA + 0][r] = wmma::__float_to_tf32(pa[t].x);
                As[4 * acA + 1][r] = wmma::__float_to_tf32(pa[t].y);
                As[4 * acA + 2][r] = wmma::__float_to_tf32(pa[t].z);
                As[4 * acA + 3][r] = wmma::__float_to_tf32(pa[t].w);
            }
            #pragma unroll
            for (int t = 0; t < 2; t++) {
                int r = wrW[t];
                float4 v = pw[t];
                v.x = wmma::__float_to_tf32(v.x);
                v.y = wmma::__float_to_tf32(v.y);
                v.z = wmma::__float_to_tf32(v.z);
                v.w = wmma::__float_to_tf32(v.w);
                *(float4*)&Ws[r][4 * wcW] = v;
            }
        }
    }

    if (addBias) {
        for (int idx = tid; idx < 8 * LDT; idx += 256) {
            int k = idx / LDT;
            int m = idx % LDT;
            As[k][m] = (k == 0 && m < 128) ? 1.0f : 0.0f;
            float bv = 0.0f;
            if (k == 0 && m < 128 && colBase + m < Nc) bv = bias[colBase + m];
            Ws[k][m] = wmma::__float_to_tf32(bv);
        }
        __syncthreads();
        wmma::fragment<wmma::matrix_a, 16, 16, 8, wmma::precision::tf32, wmma::col_major> af;
        wmma::fragment<wmma::matrix_b, 16, 16, 8, wmma::precision::tf32, wmma::row_major> bf[4];
        #pragma unroll
        for (int j = 0; j < 4; j++)
            wmma::load_matrix_sync(bf[j], &Ws[0][wc * 64 + j * 16], LDT);
        #pragma unroll
        for (int i = 0; i < 2; i++) {
            wmma::load_matrix_sync(af, &As[0][wr * 32 + i * 16], LDT);
            #pragma unroll
            for (int j = 0; j < 4; j++)
                wmma::mma_sync(acc[i][j], af, bf[j], acc[i][j]);
        }
    }

    #pragma unroll
    for (int i = 0; i < 2; i++) {
        #pragma unroll
        for (int j = 0; j < 4; j++) {
            int gr0 = rowBase + wr * 32 + i * 16;
            int gc0 = colBase + wc * 64 + j * 16;
            if (gr0 >= M || gc0 >= Nc) continue;
            if (gr0 + 15 < M && gc0 + 15 < Nc) {
                wmma::store_matrix_sync(C + (size_t)gr0 * Nc + gc0, acc[i][j], Nc, wmma::mem_row_major);
            } else {
                wmma::store_matrix_sync(scr[wid], acc[i][j], 20, wmma::mem_row_major);
                __syncwarp();
                for (int e = lane; e < 256; e += 32) {
                    int r = e >> 4, c = e & 15;
                    if (gr0 + r < M && gc0 + c < Nc)
                        C[(size_t)(gr0 + r) * Nc + gc0 + c] = scr[wid][r * 20 + c];
                }
                __syncwarp();
            }
        }
    }
}

// ---------------- layer-2 fused GEMM + bias + LN + ELU (M x 128 @ 128 x 256) ----------------
#define LDA2 68
#define LDW2 260

__global__ __launch_bounds__(256)
void gemm_ln_tf32_kernel(const float* __restrict__ A, const float* __restrict__ W,
                         const float* __restrict__ bias,
                         const float* __restrict__ gam, const float* __restrict__ bet,
                         float* __restrict__ C, int M)
{
    extern __shared__ float smem[];
    float* Asm = smem;                 // [16][LDA2]
    float* Wsm = smem + 16 * LDA2;     // [16][LDW2]
    float* stage = smem;               // [64][LDW2] (reused after mainloop)

    const int K = 128, Nc = 256;
    const int tid = threadIdx.x;
    const int wid = tid >> 5;
    const int lane = tid & 31;
    const int wr = wid >> 2;           // 0..1
    const int wc = wid & 3;            // 0..3
    const int rowBase = blockIdx.x * 64;

    const int arA = tid >> 2;          // 0..63
    const int acA = tid & 3;

    wmma::fragment<wmma::accumulator, 16, 16, 8, float> acc[2][4];
    #pragma unroll
    for (int i = 0; i < 2; i++)
        #pragma unroll
        for (int j = 0; j < 4; j++) wmma::fill_fragment(acc[i][j], 0.0f);

    // initial tile k0=0
    {
        float4 v = make_float4(0.f, 0.f, 0.f, 0.f);
        int gr = rowBase + arA;
        if (gr < M) v = *(const float4*)(A + (size_t)gr * K + 4 * acA);
        Asm[(4 * acA + 0) * LDA2 + arA] = wmma::__float_to_tf32(v.x);
        Asm[(4 * acA + 1) * LDA2 + arA] = wmma::__float_to_tf32(v.y);
        Asm[(4 * acA + 2) * LDA2 + arA] = wmma::__float_to_tf32(v.z);
        Asm[(4 * acA + 3) * LDA2 + arA] = wmma::__float_to_tf32(v.w);
    }
    #pragma unroll
    for (int t = 0; t < 4; t++) {
        int lin = t * 256 + tid;
        int r = lin >> 6;
        int c4 = lin & 63;
        float4 v = *(const float4*)(W + (size_t)r * Nc + 4 * c4);
        v.x = wmma::__float_to_tf32(v.x);
        v.y = wmma::__float_to_tf32(v.y);
        v.z = wmma::__float_to_tf32(v.z);
        v.w = wmma::__float_to_tf32(v.w);
        *(float4*)&Wsm[r * LDW2 + 4 * c4] = v;
    }

    for (int k0 = 0; k0 < K; k0 += 16) {
        __syncthreads();
        bool more = (k0 + 16) < K;
        float4 pa, pw[4];
        if (more) {
            pa = make_float4(0.f, 0.f, 0.f, 0.f);
            int gr = rowBase + arA;
            if (gr < M) pa = *(const float4*)(A + (size_t)gr * K + k0 + 16 + 4 * acA);
            #pragma unroll
            for (int t = 0; t < 4; t++) {
                int lin = t * 256 + tid;
                int r = lin >> 6;
                int c4 = lin & 63;
                pw[t] = *(const float4*)(W + (size_t)(k0 + 16 + r) * Nc + 4 * c4);
            }
        }

        #pragma unroll
        for (int ks = 0; ks < 16; ks += 8) {
            wmma::fragment<wmma::matrix_a, 16, 16, 8, wmma::precision::tf32, wmma::col_major> af[2];
            wmma::fragment<wmma::matrix_b, 16, 16, 8, wmma::precision::tf32, wmma::row_major> bf[4];
            #pragma unroll
            for (int i = 0; i < 2; i++)
                wmma::load_matrix_sync(af[i], &Asm[ks * LDA2 + wr * 32 + i * 16], LDA2);
            #pragma unroll
            for (int j = 0; j < 4; j++)
                wmma::load_matrix_sync(bf[j], &Wsm[ks * LDW2 + wc * 64 + j * 16], LDW2);
            #pragma unroll
            for (int i = 0; i < 2; i++)
                #pragma unroll
                for (int j = 0; j < 4; j++)
                    wmma::mma_sync(acc[i][j], af[i], bf[j], acc[i][j]);
        }
        __syncthreads();

        if (more) {
            Asm[(4 * acA + 0) * LDA2 + arA] = wmma::__float_to_tf32(pa.x);
            Asm[(4 * acA + 1) * LDA2 + arA] = wmma::__float_to_tf32(pa.y);
            Asm[(4 * acA + 2) * LDA2 + arA] = wmma::__float_to_tf32(pa.z);
            Asm[(4 * acA + 3) * LDA2 + arA] = wmma::__float_to_tf32(pa.w);
            #pragma unroll
            for (int t = 0; t < 4; t++) {
                int lin = t * 256 + tid;
                int r = lin >> 6;
                int c4 = lin & 63;
                float4 v = pw[t];
                v.x = wmma::__float_to_tf32(v.x);
                v.y = wmma::__float_to_tf32(v.y);
                v.z = wmma::__float_to_tf32(v.z);
                v.w = wmma::__float_to_tf32(v.w);
                *(float4*)&Wsm[r * LDW2 + 4 * c4] = v;
            }
        }
    }

    // stage accumulators to smem
    #pragma unroll
    for (int i = 0; i < 2; i++)
        #pragma unroll
        for (int j = 0; j < 4; j++)
            wmma::store_matrix_sync(&stage[(wr * 32 + i * 16) * LDW2 + wc * 64 + j * 16],
                                    acc[i][j], LDW2, wmma::mem_row_major);
    __syncthreads();

    float4 ba = ((const float4*)bias)[lane];
    float4 bb = ((const float4*)bias)[32 + lane];
    float4 ga = ((const float4*)gam)[lane];
    float4 gb = ((const float4*)gam)[32 + lane];
    float4 ea = ((const float4*)bet)[lane];
    float4 eb = ((const float4*)bet)[32 + lane];

    #pragma unroll
    for (int rr = 0; rr < 8; rr++) {
        int r = wid * 8 + rr;
        int gr = rowBase + r;
        if (gr >= M) continue;
        float4 a = *(float4*)&stage[r * LDW2 + lane * 4];
        float4 b = *(float4*)&stage[r * LDW2 + 128 + lane * 4];
        a.x += ba.x; a.y += ba.y; a.z += ba.z; a.w += ba.w;
        b.x += bb.x; b.y += bb.y; b.z += bb.z; b.w += bb.w;

        float sum = a.x + a.y + a.z + a.w + b.x + b.y + b.z + b.w;
        #pragma unroll
        for (int o = 16; o > 0; o >>= 1) sum += __shfl_xor_sync(0xFFFFFFFFu, sum, o);
        float mu = sum * (1.0f / 256.0f);
        float d0 = a.x - mu, d1 = a.y - mu, d2 = a.z - mu, d3 = a.w - mu;
        float d4 = b.x - mu, d5 = b.y - mu, d6 = b.z - mu, d7 = b.w - mu;
        float vs = d0 * d0 + d1 * d1 + d2 * d2 + d3 * d3
                 + d4 * d4 + d5 * d5 + d6 * d6 + d7 * d7;
        #pragma unroll
        for (int o = 16; o > 0; o >>= 1) vs += __shfl_xor_sync(0xFFFFFFFFu, vs, o);
        float rstd = rsqrtf(vs * (1.0f / 256.0f) + EPS);

        float4 r0, r1;
        float y;
        y = d0 * rstd * ga.x + ea.x; r0.x = (y > 0.f) ? y : expm1f(y);
        y = d1 * rstd * ga.y + ea.y; r0.y = (y > 0.f) ? y : expm1f(y);
        y = d2 * rstd * ga.z + ea.z; r0.z = (y > 0.f) ? y : expm1f(y);
        y = d3 * rstd * ga.w + ea.w; r0.w = (y > 0.f) ? y : expm1f(y);
        y = d4 * rstd * gb.x + eb.x; r1.x = (y > 0.f) ? y : expm1f(y);
        y = d5 * rstd * gb.y + eb.y; r1.y = (y > 0.f) ? y : expm1f(y);
        y = d6 * rstd * gb.z + eb.z; r1.z = (y > 0.f) ? y : expm1f(y);
        y = d7 * rstd * gb.w + eb.w; r1.w = (y > 0.f) ? y : expm1f(y);
        *(float4*)(C + (size_t)gr * 256 + lane * 4) = r0;
        *(float4*)(C + (size_t)gr * 256 + 128 + lane * 4) = r1;
    }
}

// ---------------- lin1 fused GEMM + bias + LN + ELU (M x 128 @ 128 x 64) ----------------
// Block = 128 rows x 64 cols; 8 warps, warp w owns rows w*16..+16, all 64 cols.
#define LDA3 132
#define LDW3 68

__global__ __launch_bounds__(256)
void gemm_ln64_tf32_kernel(const float* __restrict__ A, const float* __restrict__ W,
                           const float* __restrict__ bias,
                           const float* __restrict__ gam, const float* __restrict__ bet,
                           float* __restrict__ C, int M)
{
    __shared__ __align__(16) float sm[128 * LDW3];   // 8704 floats; tiles alias stage
    float* Asm = sm;                    // [16][LDA3] = 2112
    float* Wsm = sm + 16 * LDA3;        // [16][LDW3] = 1088
    float* stage = sm;                  // [128][LDW3]

    const int K = 128, Nc = 64;
    const int tid = threadIdx.x;
    const int wid = tid >> 5;
    const int lane = tid & 31;
    const int rowBase = blockIdx.x * 128;

    const int arA[2] = { (0 * 256 + tid) >> 2, (1 * 256 + tid) >> 2 };
    const int acA = tid & 3;
    const int wrW = tid >> 4;           // 0..15
    const int wcW = tid & 15;           // col float4 0..15

    wmma::fragment<wmma::accumulator, 16, 16, 8, float> acc[4];
    #pragma unroll
    for (int j = 0; j < 4; j++) wmma::fill_fragment(acc[j], 0.0f);

    // initial tile k0=0
    #pragma unroll
    for (int t = 0; t < 2; t++) {
        int r = arA[t];
        float4 v = make_float4(0.f, 0.f, 0.f, 0.f);
        int gr = rowBase + r;
        if (gr < M) v = *(const float4*)(A + (size_t)gr * K + 4 * acA);
        Asm[(4 * acA + 0) * LDA3 + r] = wmma::__float_to_tf32(v.x);
        Asm[(4 * acA + 1) * LDA3 + r] = wmma::__float_to_tf32(v.y);
        Asm[(4 * acA + 2) * LDA3 + r] = wmma::__float_to_tf32(v.z);
        Asm[(4 * acA + 3) * LDA3 + r] = wmma::__float_to_tf32(v.w);
    }
    {
        float4 v = *(const float4*)(W + (size_t)wrW * Nc + 4 * wcW);
        v.x = wmma::__float_to_tf32(v.x);
        v.y = wmma::__float_to_tf32(v.y);
        v.z = wmma::__float_to_tf32(v.z);
        v.w = wmma::__float_to_tf32(v.w);
        *(float4*)&Wsm[wrW * LDW3 + 4 * wcW] = v;
    }

    for (int k0 = 0; k0 < K; k0 += 16) {
        __syncthreads();
        bool more = (k0 + 16) < K;
        float4 pa[2], pw;
        if (more) {
            #pragma unroll
            for (int t = 0; t < 2; t++) {
                int r = arA[t];
                pa[t] = make_float4(0.f, 0.f, 0.f, 0.f);
                int gr = rowBase + r;
                if (gr < M) pa[t] = *(const float4*)(A + (size_t)gr * K + k0 + 16 + 4 * acA);
            }
            pw = *(const float4*)(W + (size_t)(k0 + 16 + wrW) * Nc + 4 * wcW);
        }

        #pragma unroll
        for (int ks = 0; ks < 16; ks += 8) {
            wmma::fragment<wmma::matrix_a, 16, 16, 8, wmma::precision::tf32, wmma::col_major> af;
            wmma::fragment<wmma::matrix_b, 16, 16, 8, wmma::precision::tf32, wmma::row_major> bf[4];
            wmma::load_matrix_sync(af, &Asm[ks * LDA3 + wid * 16], LDA3);
            #pragma unroll
            for (int j = 0; j < 4; j++)
                wmma::load_matrix_sync(bf[j], &Wsm[ks * LDW3 + j * 16], LDW3);
            #pragma unroll
            for (int j = 0; j < 4; j++)
                wmma::mma_sync(acc[j], af, bf[j], acc[j]);
        }
        __syncthreads();

        if (more) {
            #pragma unroll
            for (int t = 0; t < 2; t++) {
                int r = arA[t];
                Asm[(4 * acA + 0) * LDA3 + r] = wmma::__float_to_tf32(pa[t].x);
                Asm[(4 * acA + 1) * LDA3 + r] = wmma::__float_to_tf32(pa[t].y);
                Asm[(4 * acA + 2) * LDA3 + r] = wmma::__float_to_tf32(pa[t].z);
                Asm[(4 * acA + 3) * LDA3 + r] = wmma::__float_to_tf32(pa[t].w);
            }
            float4 v = pw;
            v.x = wmma::__float_to_tf32(v.x);
            v.y = wmma::__float_to_tf32(v.y);
            v.z = wmma::__float_to_tf32(v.z);
            v.w = wmma::__float_to_tf32(v.w);
            *(float4*)&Wsm[wrW * LDW3 + 4 * wcW] = v;
        }
    }

    // stage accumulators
    #pragma unroll
    for (int j = 0; j < 4; j++)
        wmma::store_matrix_sync(&stage[(wid * 16) * LDW3 + j * 16], acc[j],
                                LDW3, wmma::mem_row_major);
    __syncthreads();

    // epilogue: warp handles its 16 rows; lane covers 2 cols (float2)
    float2 bb = ((const float2*)bias)[lane];
    float2 gg = ((const float2*)gam)[lane];
    float2 ee = ((const float2*)bet)[lane];

    #pragma unroll
    for (int rr = 0; rr < 16; rr++) {
        int r = wid * 16 + rr;
        int gr = rowBase + r;
        if (gr >= M) continue;
        float2 v = *(float2*)&stage[r * LDW3 + 2 * lane];
        v.x += bb.x; v.y += bb.y;
        float sum = v.x + v.y;
        #pragma unroll
        for (int o = 16; o > 0; o >>= 1) sum += __shfl_xor_sync(0xFFFFFFFFu, sum, o);
        float mu = sum * (1.0f / 64.0f);
        float dx = v.x - mu, dy = v.y - mu;
        float vs = dx * dx + dy * dy;
        #pragma unroll
        for (int o = 16; o > 0; o >>= 1) vs += __shfl_xor_sync(0xFFFFFFFFu, vs, o);
        float rstd = rsqrtf(vs * (1.0f / 64.0f) + EPS);
        float2 rv;
        float y;
        y = dx * rstd * gg.x + ee.x; rv.x = (y > 0.f) ? y : expm1f(y);
        y = dy * rstd * gg.y + ee.y; rv.y = (y > 0.f) ? y : expm1f(y);
        *(float2*)(C + (size_t)gr * 64 + 2 * lane) = rv;
    }
}

// ---------------- pure CSR gather + self-loop, F=128, 4-way unrolled ----------------
__global__ void gather_kernel(const float* __restrict__ h,
                              const float* __restrict__ dinv,
                              const int* __restrict__ rowptr,
                              const int2* __restrict__ csr,
                              float* __restrict__ out, int n)
{
    int row = (blockIdx.x * blockDim.x + threadIdx.x) >> 5;
    int lane = threadIdx.x & 31;
    if (row >= n) return;

    float4 acc;
    {
        float dv = dinv[row];
        float d2 = dv * dv;
        float4 t = ((const float4*)(h + (size_t)row * 128))[lane];
        acc.x = t.x * d2; acc.y = t.y * d2; acc.z = t.z * d2; acc.w = t.w * d2;
    }

    int e = rowptr[row];
    int e1 = rowptr[row + 1];
    for (; e + 3 < e1; e += 4) {
        int2 c0 = csr[e], c1 = csr[e + 1], c2 = csr[e + 2], c3 = csr[e + 3];
        float4 t0 = ((const float4*)(h + (size_t)c0.x * 128))[lane];
        float4 t1 = ((const float4*)(h + (size_t)c1.x * 128))[lane];
        float4 t2 = ((const float4*)(h + (size_t)c2.x * 128))[lane];
        float4 t3 = ((const float4*)(h + (size_t)c3.x * 128))[lane];
        float w0 = __int_as_float(c0.y), w1 = __int_as_float(c1.y);
        float w2 = __int_as_float(c2.y), w3 = __int_as_float(c3.y);
        acc.x += t0.x * w0 + t1.x * w1 + t2.x * w2 + t3.x * w3;
        acc.y += t0.y * w0 + t1.y * w1 + t2.y * w2 + t3.y * w3;
        acc.z += t0.z * w0 + t1.z * w1 + t2.z * w2 + t3.z * w3;
        acc.w += t0.w * w0 + t1.w * w1 + t2.w * w2 + t3.w * w3;
    }
    for (; e < e1; e++) {
        int2 c0 = csr[e];
        float w0 = __int_as_float(c0.y);
        float4 t0 = ((const float4*)(h + (size_t)c0.x * 128))[lane];
        acc.x += t0.x * w0; acc.y += t0.y * w0;
        acc.z += t0.z * w0; acc.w += t0.w * w0;
    }
    ((float4*)(out + (size_t)row * 128))[lane] = acc;
}

// ---------------- fused CSR gather + bias + LN + ELU, F=128, 4-way unrolled ----------------
__global__ void gather_ln_elu_kernel(const float* __restrict__ h,
                                     const float* __restrict__ dinv,
                                     const int* __restrict__ rowptr,
                                     const int2* __restrict__ csr,
                                     const float* __restrict__ bias,
                                     const float* __restrict__ g,
                                     const float* __restrict__ be,
                                     float* __restrict__ out, int n)
{
    int row = (blockIdx.x * blockDim.x + threadIdx.x) >> 5;
    int lane = threadIdx.x & 31;
    if (row >= n) return;

    float4 acc;
    {
        float dv = dinv[row];
        float d2 = dv * dv;
        float4 t = ((const float4*)(h + (size_t)row * 128))[lane];
        acc.x = t.x * d2; acc.y = t.y * d2; acc.z = t.z * d2; acc.w = t.w * d2;
    }

    int e = rowptr[row];
    int e1 = rowptr[row + 1];
    for (; e + 3 < e1; e += 4) {
        int2 c0 = csr[e], c1 = csr[e + 1], c2 = csr[e + 2], c3 = csr[e + 3];
        float4 t0 = ((const float4*)(h + (size_t)c0.x * 128))[lane];
        float4 t1 = ((const float4*)(h + (size_t)c1.x * 128))[lane];
        float4 t2 = ((const float4*)(h + (size_t)c2.x * 128))[lane];
        float4 t3 = ((const float4*)(h + (size_t)c3.x * 128))[lane];
        float w0 = __int_as_float(c0.y), w1 = __int_as_float(c1.y);
        float w2 = __int_as_float(c2.y), w3 = __int_as_float(c3.y);
        acc.x += t0.x * w0 + t1.x * w1 + t2.x * w2 + t3.x * w3;
        acc.y += t0.y * w0 + t1.y * w1 + t2.y * w2 + t3.y * w3;
        acc.z += t0.z * w0 + t1.z * w1 + t2.z * w2 + t3.z * w3;
        acc.w += t0.w * w0 + t1.w * w1 + t2.w * w2 + t3.w * w3;
    }
    for (; e < e1; e++) {
        int2 c0 = csr[e];
        float w0 = __int_as_float(c0.y);
        float4 t0 = ((const float4*)(h + (size_t)c0.x * 128))[lane];
        acc.x += t0.x * w0; acc.y += t0.y * w0;
        acc.z += t0.z * w0; acc.w += t0.w * w0;
    }

    {
        float4 b4 = ((const float4*)bias)[lane];
        acc.x += b4.x; acc.y += b4.y; acc.z += b4.z; acc.w += b4.w;
    }

    float sum = acc.x + acc.y + acc.z + acc.w;
    #pragma unroll
    for (int o = 16; o > 0; o >>= 1) sum += __shfl_xor_sync(0xFFFFFFFFu, sum, o);
    float mu = sum * (1.0f / 128.0f);
    float dx = acc.x - mu, dy = acc.y - mu, dz = acc.z - mu, dw = acc.w - mu;
    float vsum = dx * dx + dy * dy + dz * dz + dw * dw;
    #pragma unroll
    for (int o = 16; o > 0; o >>= 1) vsum += __shfl_xor_sync(0xFFFFFFFFu, vsum, o);
    float rstd = rsqrtf(vsum * (1.0f / 128.0f) + EPS);

    float4 g4 = ((const float4*)g)[lane];
    float4 b4 = ((const float4*)be)[lane];
    float4 r;
    float y;
    y = dx * rstd * g4.x + b4.x; r.x = (y > 0.f) ? y : expm1f(y);
    y = dy * rstd * g4.y + b4.y; r.y = (y > 0.f) ? y : expm1f(y);
    y = dz * rstd * g4.z + b4.z; r.z = (y > 0.f) ? y : expm1f(y);
    y = dw * rstd * g4.w + b4.w; r.w = (y > 0.f) ? y : expm1f(y);
    ((float4*)(out + (size_t)row * 128))[lane] = r;
}

// ---------------- host ----------------
extern "C" void kernel_launch(void* const* d_in, const int* in_sizes, int n_in,
                              void* d_out, int out_size)
{
    const float* x    = (const float*)d_in[0];
    const int* eidx   = (const int*)d_in[1];
    const float* W1   = (const float*)d_in[2];
    const float* b1   = (const float*)d_in[3];
    const float* g1   = (const float*)d_in[4];
    const float* be1  = (const float*)d_in[5];
    const float* W2   = (const float*)d_in[6];
    const float* b2   = (const float*)d_in[7];
    const float* g2   = (const float*)d_in[8];
    const float* be2  = (const float*)d_in[9];
    const float* W3   = (const float*)d_in[10];
    const float* b3   = (const float*)d_in[11];
    const float* g3   = (const float*)d_in[12];
    const float* be3  = (const float*)d_in[13];
    const float* Wl1  = (const float*)d_in[14];
    const float* bl1  = (const float*)d_in[15];
    const float* g4   = (const float*)d_in[16];
    const float* be4  = (const float*)d_in[17];
    const float* Wl2  = (const float*)d_in[18];
    const float* bl2  = (const float*)d_in[19];
    float* out = (float*)d_out;

    const int N = in_sizes[0] / 128;      // 50000
    const int E = in_sizes[1] / 2;        // 800000
    const int H = 128, H2 = 256, HL = 64, OUT = 500;

    const int* src = eidx;
    const int* dst = eidx + E;

    float *bufA, *bufB, *dinv;
    int *deg, *rowptr, *cursor, *incl, *bsums;
    int2* csr;
    cudaGetSymbolAddress((void**)&bufA, g_bufA);
    cudaGetSymbolAddress((void**)&bufB, g_bufB);
    cudaGetSymbolAddress((void**)&dinv, g_dinv);
    cudaGetSymbolAddress((void**)&deg, g_deg);
    cudaGetSymbolAddress((void**)&rowptr, g_rowptr);
    cudaGetSymbolAddress((void**)&cursor, g_cursor);
    cudaGetSymbolAddress((void**)&csr, g_csr);
    cudaGetSymbolAddress((void**)&incl, g_incl);
    cudaGetSymbolAddress((void**)&bsums, g_bsums);

    static const int DYN_SMEM = 64 * 260 * (int)sizeof(float);   // 66560
    cudaFuncSetAttribute(gemm_ln_tf32_kernel,
                         cudaFuncAttributeMaxDynamicSharedMemorySize, DYN_SMEM);

    // side stream + events for prep/GEMM overlap (created once; reused every call)
    static cudaStream_t s2 = nullptr;
    static cudaEvent_t evFork = nullptr, evJoin = nullptr;
    if (s2 == nullptr) {
        cudaStreamCreateWithFlags(&s2, cudaStreamNonBlocking);
        cudaEventCreateWithFlags(&evFork, cudaEventDisableTiming);
        cudaEventCreateWithFlags(&evJoin, cudaEventDisableTiming);
    }

    // ---- fork: CSR build on s2, layer-1 GEMM on main stream ----
    cudaEventRecord(evFork, 0);
    cudaStreamWaitEvent(s2, evFork, 0);

    zero_deg_kernel<<<(N + 255) / 256, 256, 0, s2>>>(deg, N);
    count_deg_kernel<<<(E + 255) / 256, 256, 0, s2>>>(dst, deg, E);
    dinv_kernel<<<(N + 255) / 256, 256, 0, s2>>>(deg, dinv, N);
    int nb = (N + 1023) / 1024;
    scan_partial_kernel<<<nb, 1024, 0, s2>>>(deg, incl, bsums, N);
    scan_bsums_kernel<<<1, 32, 0, s2>>>(bsums, nb);
    scan_finalize_kernel<<<(N + 255) / 256, 256, 0, s2>>>(deg, incl, bsums, rowptr, cursor, N);
    fill_csr_kernel<<<(E + 255) / 256, 256, 0, s2>>>(src, dst, dinv, cursor, csr, E);
    cudaEventRecord(evJoin, s2);

    auto gemmGrid = [](int M, int Nc) { return dim3((Nc + 127) / 128, (M + 127) / 128); };
    int warpBlocks = (N + 7) / 8;

    // --- GCN layer 1 GEMM (independent of CSR) ---
    gemm_tf32_kernel<<<gemmGrid(N, H), 256>>>(x, W1, nullptr, bufA, N, 128, H, 0);

    // ---- join: gather needs CSR + dinv ----
    cudaStreamWaitEvent(0, evJoin, 0);

    gather_ln_elu_kernel<<<warpBlocks, 256>>>(bufA, dinv, rowptr, csr, b1, g1, be1, bufB, N);

    // --- GCN layer 2 (reordered + fused): h2 = LN/ELU( (Â h1) W2 + b2 ) ---
    gather_kernel<<<warpBlocks, 256>>>(bufB, dinv, rowptr, csr, bufA, N);
    gemm_ln_tf32_kernel<<<(N + 63) / 64, 256, DYN_SMEM>>>(bufA, W2, b2, g2, be2, bufB, N);

    // --- GCN layer 3: h3 = LN/ELU( Â(h2 W3) + b3 ) ---
    gemm_tf32_kernel<<<gemmGrid(N, H), 256>>>(bufB, W3, nullptr, bufA, N, H2, H, 0);
    gather_ln_elu_kernel<<<warpBlocks, 256>>>(bufA, dinv, rowptr, csr, b3, g3, be3, bufB, N);

    // --- Linear 128 -> 64 + LN + ELU (fused) ---
    gemm_ln64_tf32_kernel<<<(N + 127) / 128, 256>>>(bufB, Wl1, bl1, g4, be4, bufA, N);

    // --- Linear 64 -> 500 (output) ---
    gemm_tf32_kernel<<<gemmGrid(N, OUT), 256>>>(bufA, Wl2, bl2, out, N, HL, OUT, 1);

    (void)n_in; (void)out_size;
}